// round 7
// baseline (speedup 1.0000x reference)
#include <cuda_runtime.h>
#include <cstdint>

// ============================================================================
// C[8192,4096] = X[8192,4096] @ W[4096,4096], fp32 in/out, tf32 mma.sync.
// R7: fat warp tile 64x64 (4 warps/CTA, 128 thr, ~206 regs) to cut the
//     LDSM-per-MMA ratio (smem crossbar was ~83% busy at full tensor rate).
//     2 CTAs/SM, 3-stage cp.async. Fused preprocessing (round X + transpose W).
// ============================================================================
#define M_DIM 8192
#define K_DIM 4096
#define N_DIM 4096

#define BM 128
#define BN 128
#define BK 32                         // 32 floats = 128 B rows
#define STAGES 3
#define ITERS (K_DIM / BK)            // 128
#define NT (N_DIM / BN)               // 32
#define MT (M_DIM / BM)               // 64
#define THREADS 128

#define A_BYTES (BM * BK * 4)         // 16384
#define B_BYTES (BN * BK * 4)         // 16384
#define STAGE_BYTES (A_BYTES + B_BYTES)   // 32768
#define SMEM_TOTAL (STAGES * STAGE_BYTES) // 98304

// Scratch: Bt[n][k] = round_tf32(W[k][n]); Xr = round_tf32(X)
__device__ float g_Bt[(size_t)N_DIM * K_DIM];   // 64 MB
__device__ float g_Xr[(size_t)M_DIM * K_DIM];   // 128 MB

// ============================================================================
// PTX helpers
// ============================================================================
__device__ __forceinline__ uint32_t smem_to_u32(const void* p) {
    uint32_t a;
    asm("{ .reg .u64 t; cvta.to.shared.u64 t, %1; cvt.u32.u64 %0, t; }"
        : "=r"(a) : "l"(p));
    return a;
}

#define CP_ASYNC16(smem_addr, gptr) \
    asm volatile("cp.async.cg.shared.global [%0], [%1], 16;" \
                 :: "r"(smem_addr), "l"(gptr) : "memory")
#define CP_COMMIT() asm volatile("cp.async.commit_group;" ::: "memory")
#define CP_WAIT(n)  asm volatile("cp.async.wait_group %0;" :: "n"(n) : "memory")

#define LDSM_X4(r0, r1, r2, r3, addr) \
    asm volatile("ldmatrix.sync.aligned.m8n8.x4.shared.b16 {%0,%1,%2,%3}, [%4];" \
                 : "=r"(r0), "=r"(r1), "=r"(r2), "=r"(r3) : "r"(addr))

__device__ __forceinline__ float round_tf32(float x) {
    uint32_t u = __float_as_uint(x);
    asm("cvt.rna.tf32.f32 %0, %1;" : "=r"(u) : "r"(u));
    return __uint_as_float(u);
}

#define MMA_TF32(c, a, b) \
    asm volatile( \
        "mma.sync.aligned.m16n8k8.row.col.f32.tf32.tf32.f32 " \
        "{%0,%1,%2,%3}, {%4,%5,%6,%7}, {%8,%9}, {%0,%1,%2,%3};" \
        : "+f"((c)[0]), "+f"((c)[1]), "+f"((c)[2]), "+f"((c)[3]) \
        : "r"((a)[0]), "r"((a)[1]), "r"((a)[2]), "r"((a)[3]), \
          "r"((b)[0]), "r"((b)[1]))

// ============================================================================
// Kernel 0 (fused preprocessing):
//   blocks [0, NXB): round X -> Xr (float4)
//   blocks [NXB, NXB+NTB): transpose+round W[k][n] -> Bt[n][k] (32x32 tiles)
// ============================================================================
#define NXB ((M_DIM * (size_t)K_DIM / 4) / 256)      // 32768
#define NTB ((K_DIM / 32) * (N_DIM / 32))            // 16384

__global__ void __launch_bounds__(256) preprocess_kernel(
    const float* __restrict__ X, float* __restrict__ Xr,
    const float* __restrict__ W, float* __restrict__ Bt)
{
    __shared__ float t[32][33];
    unsigned bid = blockIdx.x;
    int tid = threadIdx.x;

    if (bid < NXB) {
        size_t i = (size_t)bid * 256 + tid;
        float4 v = ((const float4*)X)[i];
        v.x = round_tf32(v.x); v.y = round_tf32(v.y);
        v.z = round_tf32(v.z); v.w = round_tf32(v.w);
        ((float4*)Xr)[i] = v;
    } else {
        unsigned b2 = bid - NXB;
        int bx = (b2 % (N_DIM / 32)) * 32;   // n block
        int by = (b2 / (N_DIM / 32)) * 32;   // k block
        int tx = tid & 31, ty = tid >> 5;    // 32 x 8
        #pragma unroll
        for (int j = 0; j < 32; j += 8)
            t[ty + j][tx] = round_tf32(W[(size_t)(by + ty + j) * N_DIM + (bx + tx)]);
        __syncthreads();
        #pragma unroll
        for (int j = 0; j < 32; j += 8)
            Bt[(size_t)(bx + ty + j) * K_DIM + (by + tx)] = t[tx][ty + j];
    }
}

// ============================================================================
// Kernel 1: tf32 mma.sync GEMM
//   128 threads = 4 warps in 2(m) x 2(n); warp tile 64x64; 3-stage cp.async;
//   2 CTAs/SM. Operands pre-rounded to tf32.
// ============================================================================
__global__ void __launch_bounds__(THREADS, 2) gemm_tf32_kernel(
    const float* __restrict__ X,
    const float* __restrict__ Bt,
    float* __restrict__ C)
{
    extern __shared__ __align__(1024) char smem[];
    uint32_t sb = smem_to_u32(smem);

    int tid  = threadIdx.x;
    int wid  = tid >> 5;
    int lane = tid & 31;
    int bid  = blockIdx.x;
    int tn   = bid % NT;
    int tm   = bid / NT;

    int wm = wid & 1;              // m group 0..1
    int wn = wid >> 1;             // n group 0..1
    int warp_m0 = wm * 64;
    int warp_n0 = wn * 64;

    // ---- cp.async precompute: 1024 16B chunks per operand per stage,
    //      8 per thread. A and B share identical smem-offset geometry. ----
    uint32_t off[8];
    uint32_t gA[8], gB[8];     // 32-bit float-index offsets into X / Bt
    #pragma unroll
    for (int p = 0; p < 8; p++) {
        int ca = tid + p * THREADS;
        int row = ca >> 3, c = ca & 7;
        off[p] = row * 128 + ((c ^ (row & 7)) << 4);
        gA[p] = (uint32_t)(tm * BM + row) * K_DIM + c * 4;
        gB[p] = (uint32_t)(tn * BN + row) * K_DIM + c * 4;
    }

    // ---- ldmatrix per-lane address components ----
    uint32_t a_sw  = lane & 7;
    uint32_t a_co  = lane >> 4;
    uint32_t aBaseRel = (uint32_t)(warp_m0 + (lane & 15)) * 128;
    uint32_t b_sw  = lane & 7;
    uint32_t b_ch  = (lane >> 3) & 1;
    uint32_t bBaseRel = (uint32_t)(warp_n0 + (lane & 7) + ((lane >> 4) << 3)) * 128;

    float acc[4][8][4];
    #pragma unroll
    for (int mt = 0; mt < 4; mt++)
        #pragma unroll
        for (int nt = 0; nt < 8; nt++)
            #pragma unroll
            for (int v = 0; v < 4; v++) acc[mt][nt][v] = 0.0f;

    // ---- prologue: fill 2 stages ----
    #pragma unroll
    for (int i = 0; i < STAGES - 1; i++) {
        uint32_t sA = sb + i * STAGE_BYTES;
        uint32_t sB = sA + A_BYTES;
        #pragma unroll
        for (int p = 0; p < 8; p++) { CP_ASYNC16(sA + off[p], X  + gA[p]); gA[p] += BK; }
        #pragma unroll
        for (int p = 0; p < 8; p++) { CP_ASYNC16(sB + off[p], Bt + gB[p]); gB[p] += BK; }
        CP_COMMIT();
    }

    int s_comp = 0;
    int s_load = STAGES - 1;

    // ---- main loop ----
    #pragma unroll 1
    for (int i = 0; i < ITERS; i++) {
        CP_WAIT(STAGES - 2);
        __syncthreads();

        if (i + STAGES - 1 < ITERS) {
            uint32_t sA = sb + s_load * STAGE_BYTES;
            uint32_t sB = sA + A_BYTES;
            #pragma unroll
            for (int p = 0; p < 8; p++) { CP_ASYNC16(sA + off[p], X  + gA[p]); gA[p] += BK; }
            #pragma unroll
            for (int p = 0; p < 8; p++) { CP_ASYNC16(sB + off[p], Bt + gB[p]); gB[p] += BK; }
        }
        CP_COMMIT();

        uint32_t As = sb + s_comp * STAGE_BYTES;
        uint32_t Bs = As + A_BYTES;
        uint32_t aBase = As + aBaseRel;
        uint32_t bBase = Bs + bBaseRel;

        #pragma unroll
        for (int ks = 0; ks < 4; ks++) {
            uint32_t aoff = (((uint32_t)ks * 2 + a_co) ^ a_sw) << 4;
            uint32_t boff = (((uint32_t)ks * 2 + b_ch) ^ b_sw) << 4;
            uint32_t a[4][4];
            #pragma unroll
            for (int mt = 0; mt < 4; mt++) {
                uint32_t addr = aBase + mt * 2048 + aoff;
                LDSM_X4(a[mt][0], a[mt][1], a[mt][2], a[mt][3], addr);
            }
            uint32_t b[8][2];
            #pragma unroll
            for (int j = 0; j < 4; j++) {
                uint32_t addr = bBase + j * 2048 + boff;
                uint32_t r0, r1, r2, r3;
                LDSM_X4(r0, r1, r2, r3, addr);
                b[2 * j][0] = r0;      b[2 * j][1] = r1;
                b[2 * j + 1][0] = r2;  b[2 * j + 1][1] = r3;
            }
            #pragma unroll
            for (int mt = 0; mt < 4; mt++)
                #pragma unroll
                for (int nt = 0; nt < 8; nt++)
                    MMA_TF32(acc[mt][nt], a[mt], b[nt]);
        }

        if (++s_comp == STAGES) s_comp = 0;
        if (++s_load == STAGES) s_load = 0;
    }

    // ---- epilogue: direct global stores (float2) ----
    int row0 = tm * BM + warp_m0 + (lane >> 2);
    int col0 = tn * BN + warp_n0 + (lane & 3) * 2;
    #pragma unroll
    for (int mt = 0; mt < 4; mt++) {
        #pragma unroll
        for (int nt = 0; nt < 8; nt++) {
            int r = row0 + mt * 16;
            int c = col0 + nt * 8;
            float2* d0 = (float2*)(C + (size_t)r * N_DIM + c);
            float2* d1 = (float2*)(C + (size_t)(r + 8) * N_DIM + c);
            *d0 = make_float2(acc[mt][nt][0], acc[mt][nt][1]);
            *d1 = make_float2(acc[mt][nt][2], acc[mt][nt][3]);
        }
    }
}

// ============================================================================
// Host launcher
// ============================================================================
extern "C" void kernel_launch(void* const* d_in, const int* in_sizes, int n_in,
                              void* d_out, int out_size)
{
    const float* X = (const float*)d_in[0];   // [8192, 4096]
    const float* W = (const float*)d_in[1];   // [4096, 4096]
    float* C = (float*)d_out;                 // [8192, 4096]

    void* bt_ptr = nullptr;
    cudaGetSymbolAddress(&bt_ptr, g_Bt);
    void* xr_ptr = nullptr;
    cudaGetSymbolAddress(&xr_ptr, g_Xr);

    // 0) fused: round X -> Xr  +  transpose/round W -> Bt
    preprocess_kernel<<<(unsigned)(NXB + NTB), 256>>>(
        X, (float*)xr_ptr, W, (float*)bt_ptr);

    // 1) GEMM on pre-rounded operands, 2 CTAs/SM
    cudaFuncSetAttribute(gemm_tf32_kernel,
                         cudaFuncAttributeMaxDynamicSharedMemorySize, SMEM_TOTAL);
    gemm_tf32_kernel<<<MT * NT, THREADS, SMEM_TOTAL>>>(
        (const float*)xr_ptr, (const float*)bt_ptr, C);
}